// round 6
// baseline (speedup 1.0000x reference)
#include <cuda_runtime.h>
#include <math.h>
#include <stdint.h>

#define NA 50000
#define GD 15
#define NC (GD*GD*GD)
#define MP 2000000
#define CAP_A 96
#define CAP_W 768
#define CAP_C 64
#define NBE_A ((NA + 31) / 32)     // 1563 emit blocks (32 atoms)
#define NBE_W ((NC + 31) / 32)     // 106 emit blocks (32 cells)
#define NFA   NBE_A                // fine bins over atoms (32 each)
#define NCA   ((NA + 1023) / 1024) // 49 coarse bins over atoms
#define NFW   NBE_W                // fine bins over cells (32 each)
#define NB_TAIL 512

// ---------------- scratch (no allocs; zero-init at load) ----------------
__device__ int    g_cnt[NC];                       // zero at replay start (re-zeroed in emit tail)
__device__ float4 g_cell4[(size_t)NC * CAP_C];     // unsorted per-cell (x,y,z,idbits)
__device__ float4 g_sp4[(size_t)NC * CAP_C];       // id-sorted per-cell
__device__ int    g_akept[NA];
__device__ int    g_wkept[NC];
__device__ int    g_fineA[NFA];                    // zeroed in k_assign each replay
__device__ int    g_coarseA[NCA];
__device__ int    g_fineW[NFW];
__device__ float4 g_scrA[(size_t)NA * CAP_A];      // per-atom surround staging
__device__ float4 g_scrW[(size_t)NC * CAP_W];      // per-cell within staging

__constant__ int c_off[13][3] = {
  {-1,0,0},{-1,-1,0},{0,-1,0},{1,-1,0},{-1,1,-1},{0,1,-1},{1,1,-1},
  {-1,0,-1},{0,0,-1},{1,0,-1},{-1,-1,-1},{0,-1,-1},{1,-1,-1}};

// ---------------- helpers ----------------
__device__ __forceinline__ int cellcoord(double v) {
  const double inv = 1.0/80.0;
  double f = __dmul_rn(v, inv);
  f = f - floor(f);
  if (f >= 1.0) f -= 1.0;
  if (f <  0.0) f += 1.0;
  return (int)floor(__dmul_rn(f, (double)GD));
}

__device__ __forceinline__ bool keep_pair(float ax, float ay, float az,
                                          float bx, float by, float bz,
                                          float fsx, float fsy, float fsz,
                                          float& dx, float& dy, float& dz) {
  dx = (ax - bx) + fsx;
  dy = (ay - by) + fsy;
  dz = (az - bz) + fsz;
  float sq = dx*dx + dy*dy + dz*dz;
  if (sq <= 27.0290f) return true;     // (5.2 - 1e-3)^2
  if (sq >  27.0510f) return false;    // (5.2 + 1e-3)^2
  double ddx = __dadd_rn(__dsub_rn((double)ax, (double)bx), (double)fsx);
  double ddy = __dadd_rn(__dsub_rn((double)ay, (double)by), (double)fsy);
  double ddz = __dadd_rn(__dsub_rn((double)az, (double)bz), (double)fsz);
  double dsq = __dadd_rn(__dadd_rn(__dmul_rn(ddx,ddx), __dmul_rn(ddy,ddy)), __dmul_rn(ddz,ddz));
  return sqrt(dsq) <= 5.2;
}

__device__ __forceinline__ int warp_sum_bcast(int v) {
  #pragma unroll
  for (int o = 16; o >= 1; o >>= 1) v += __shfl_down_sync(0xffffffffu, v, o);
  return __shfl_sync(0xffffffffu, v, 0);
}

// ---------------- 1. assign: cell id + fixed-stride staging + bin reset -------
__global__ void k_assign(const float* __restrict__ coords) {
  int i = blockIdx.x*blockDim.x + threadIdx.x;
  // reset offset bins for this replay (before k_pairs runs)
  if (i < NFA)            g_fineA[i] = 0;
  else if (i < NFA + NCA) g_coarseA[i - NFA] = 0;
  else if (i < NFA + NCA + NFW) g_fineW[i - NFA - NCA] = 0;
  if (i >= NA) return;
  float x = coords[3*i+0], y = coords[3*i+1], z = coords[3*i+2];
  int cx = cellcoord((double)x);
  int cy = cellcoord((double)y);
  int cz = cellcoord((double)z);
  int f = (cx*GD + cy)*GD + cz;
  int slot = atomicAdd(&g_cnt[f], 1);
  if (slot < CAP_C)
    g_cell4[f*CAP_C + slot] = make_float4(x, y, z, __int_as_float(i));
}

// ---------------- 2. per-cell id rank-sort (stable = ascending id) ------------
__global__ void __launch_bounds__(256) k_sortcell() {
  __shared__ float4 sc[8][CAP_C];
  int w = (blockIdx.x*blockDim.x + threadIdx.x) >> 5;
  int lane = threadIdx.x & 31;
  int wl = threadIdx.x >> 5;
  if (w >= NC) return;
  int n = g_cnt[w]; if (n > CAP_C) n = CAP_C;
  int s = w * CAP_C;
  for (int k = lane; k < n; k += 32) sc[wl][k] = g_cell4[s+k];
  __syncwarp();
  for (int k = lane; k < n; k += 32) {
    float4 v = sc[wl][k];
    int id = __float_as_int(v.w);
    int rank = 0;
    for (int m = 0; m < n; m++) rank += (__float_as_int(sc[wl][m].w) < id);
    g_sp4[s+rank] = v;
  }
}

// ---------------- 3. pairs: one block per cell, smem candidates ----------------
__global__ void __launch_bounds__(256) k_pairs() {
  const unsigned FULL = 0xffffffffu;
  int tid = threadIdx.x, lane = tid & 31, wl = tid >> 5;
  int c = blockIdx.x;

  __shared__ float4 s_cand[13*CAP_C];   // 13 neighbor segments, contiguous
  __shared__ float4 s_own[CAP_C];       // own cell
  __shared__ int    s_pre[13], s_end[13], s_gbase[13];
  __shared__ float  s_fx[13], s_fy[13], s_fz[13];
  __shared__ int    s_total, s_nown;

  int cz = c % GD, cy = (c / GD) % GD, cx = c / (GD*GD);

  if (wl == 0) {
    int segC = 0, segB = 0;
    float fx = 0.f, fy = 0.f, fz = 0.f;
    if (lane < 13) {
      int nx = cx + c_off[lane][0], ny = cy + c_off[lane][1], nz = cz + c_off[lane][2];
      int sx = 0, sy = 0, sz = 0;
      if (nx < 0) { nx += GD; sx = 1; } else if (nx >= GD) { nx -= GD; sx = -1; }
      if (ny < 0) { ny += GD; sy = 1; } else if (ny >= GD) { ny -= GD; sy = -1; }
      if (nz < 0) { nz += GD; sz = 1; } else if (nz >= GD) { nz -= GD; sz = -1; }
      int nc = (nx*GD + ny)*GD + nz;
      segB = nc * CAP_C;
      segC = g_cnt[nc]; if (segC > CAP_C) segC = CAP_C;
      fx = (float)sx * 80.0f; fy = (float)sy * 80.0f; fz = (float)sz * 80.0f;
    }
    int pre = segC;
    #pragma unroll
    for (int o = 1; o < 16; o <<= 1) {
      int y = __shfl_up_sync(FULL, pre, o);
      if (lane >= o) pre += y;
    }
    int total = __shfl_sync(FULL, pre, 12);
    if (lane < 13) {
      s_pre[lane] = pre - segC;
      s_end[lane] = pre;
      s_gbase[lane] = segB;
      s_fx[lane] = fx; s_fy[lane] = fy; s_fz[lane] = fz;
    }
    if (lane == 0) {
      s_total = total;
      int n = g_cnt[c]; if (n > CAP_C) n = CAP_C;
      s_nown = n;
    }
  }
  __syncthreads();

  int total = s_total, nown = s_nown;
  // cooperative load: neighbors contiguous, own cell separate
  for (int t = tid; t < total; t += 256) {
    int o = 0;
    while (o < 12 && t >= s_end[o]) o++;
    s_cand[t] = g_sp4[s_gbase[o] + (t - s_pre[o])];
  }
  for (int t = tid; t < nown; t += 256)
    s_own[t] = g_sp4[c*CAP_C + t];
  __syncthreads();

  // Phase A: surround pairs; warp per atom slot, round-robin
  for (int i = wl; i < nown; i += 8) {
    float4 av = s_own[i];
    int a = __float_as_int(av.w);
    float4* scr = &g_scrA[(size_t)a * CAP_A];
    int wp = 0;
    int o = 0;                          // monotone per-lane segment cursor
    for (int t0 = 0; t0 < total; t0 += 32) {
      int t = t0 + lane;
      bool kp = false; float bid = 0.f; float dx = 0.f, dy = 0.f, dz = 0.f;
      if (t < total) {
        while (o < 12 && t >= s_end[o]) o++;
        float4 v = s_cand[t];
        kp = keep_pair(av.x, av.y, av.z, v.x, v.y, v.z,
                       s_fx[o], s_fy[o], s_fz[o], dx, dy, dz);
        bid = v.w;
      }
      unsigned m = __ballot_sync(FULL, kp);
      if (kp) {
        int p = wp + __popc(m & ((1u << lane) - 1u));
        scr[p] = make_float4(bid, dx, dy, dz);
      }
      wp += __popc(m);
    }
    if (lane == 0) {
      g_akept[a] = wp;
      atomicAdd(&g_fineA[a >> 5], wp);
      atomicAdd(&g_coarseA[a >> 10], wp);
    }
  }

  // Phase B: within-cell pairs (warp 0), tril order (i asc, j asc, i>j)
  if (wl == 0) {
    int n = nown;
    int T = n*(n-1)/2;
    float4* scr = &g_scrW[(size_t)c * CAP_W];
    int wp = 0;
    for (int t0 = 0; t0 < T; t0 += 32) {
      int t = t0 + lane;
      bool kp = false; int ij = 0; float dx = 0.f, dy = 0.f, dz = 0.f;
      if (t < T) {
        int i = (int)((1.0f + sqrtf(8.0f*(float)t + 1.0f)) * 0.5f);
        while (i*(i-1)/2 > t) i--;
        while ((i+1)*i/2 <= t) i++;
        int j = t - i*(i-1)/2;
        float4 va = s_own[i];
        float4 vb = s_own[j];
        kp = keep_pair(va.x, va.y, va.z, vb.x, vb.y, vb.z, 0.f, 0.f, 0.f, dx, dy, dz);
        ij = i | (j << 8);
      }
      unsigned m = __ballot_sync(FULL, kp);
      if (kp) {
        int p = wp + __popc(m & ((1u << lane) - 1u));
        scr[p] = make_float4(__int_as_float(ij), dx, dy, dz);
      }
      wp += __popc(m);
    }
    if (lane == 0) {
      g_wkept[c] = wp;
      atomicAdd(&g_fineW[c >> 5], wp);
    }
  }
}

// ---------------- 4. emit: 32 atoms/cells per block + tail --------------------
__device__ __forceinline__ void emit_one(float* __restrict__ out, int p,
                                         float fa, float fb,
                                         float dx, float dy, float dz) {
  out[p]        = fa;
  out[MP + p]   = fb;
  out[2*MP + p] = sqrtf(dx*dx + dy*dy + dz*dz);
  out[3*MP + 3*p + 0] = dx;
  out[3*MP + 3*p + 1] = dy;
  out[3*MP + 3*p + 2] = dz;
  out[6*MP + p] = 1.0f;
}

__global__ void __launch_bounds__(256) k_emit(float* __restrict__ out) {
  const unsigned FULL = 0xffffffffu;
  int lane = threadIdx.x & 31;
  int wl = threadIdx.x >> 5;
  int b = blockIdx.x;
  __shared__ int sh_off[32], sh_n[32];

  if (b < NBE_A) {
    // ---- surround emit: 32 atoms, exactly one fine bin
    int a0 = b * 32;
    if (wl == 0) {
      int cb = b >> 5;                        // coarse bin of this fine bin
      int acc = 0;
      for (int q = lane; q < NCA; q += 32) acc += (q < cb) ? g_coarseA[q] : 0;
      if (lane < (b & 31)) acc += g_fineA[(cb << 5) + lane];
      int base = warp_sum_bcast(acc);
      int a = a0 + lane;
      int cnt = (a < NA) ? g_akept[a] : 0;
      int pre = cnt;
      #pragma unroll
      for (int o = 1; o < 32; o <<= 1) {
        int y = __shfl_up_sync(FULL, pre, o);
        if (lane >= o) pre += y;
      }
      sh_off[lane] = base + pre - cnt;
      sh_n[lane] = cnt;
    }
    __syncthreads();
    #pragma unroll
    for (int r = 0; r < 4; r++) {
      int li = wl*4 + r;
      int a = a0 + li;
      if (a >= NA) continue;
      int n = sh_n[li], off = sh_off[li];
      const float4* scr = &g_scrA[(size_t)a * CAP_A];
      float fa = (float)a;
      for (int k = lane; k < n; k += 32) {
        float4 v = scr[k];
        emit_one(out, off + k, fa, (float)__float_as_int(v.x), v.y, v.z, v.w);
      }
    }
  } else if (b < NBE_A + NBE_W) {
    // ---- within emit: 32 cells, exactly one fine bin
    int eb = b - NBE_A;
    int w0 = eb * 32;
    if (wl == 0) {
      int acc = 0;
      for (int q = lane; q < NCA; q += 32) acc += g_coarseA[q];           // totalS
      for (int q = lane; q < NFW; q += 32) acc += (q < eb) ? g_fineW[q] : 0;
      int base = warp_sum_bcast(acc);
      int w = w0 + lane;
      int cnt = (w < NC) ? g_wkept[w] : 0;
      int pre = cnt;
      #pragma unroll
      for (int o = 1; o < 32; o <<= 1) {
        int y = __shfl_up_sync(FULL, pre, o);
        if (lane >= o) pre += y;
      }
      sh_off[lane] = base + pre - cnt;
      sh_n[lane] = cnt;
    }
    __syncthreads();
    #pragma unroll
    for (int r = 0; r < 4; r++) {
      int li = wl*4 + r;
      int w = w0 + li;
      if (w >= NC) continue;
      int n = sh_n[li], off = sh_off[li];
      int s = w * CAP_C;
      const float4* scr = &g_scrW[(size_t)w * CAP_W];
      for (int k = lane; k < n; k += 32) {
        float4 v = scr[k];
        int ij = __float_as_int(v.x);
        float fa = (float)__float_as_int(g_sp4[s + (ij & 0xff)].w);
        float fb = (float)__float_as_int(g_sp4[s + (ij >> 8)].w);
        emit_one(out, off + k, fa, fb, v.y, v.z, v.w);
      }
    }
  } else {
    // ---- tail: zero [totalAll, MP) + re-zero g_cnt for next replay
    int tb = b - NBE_A - NBE_W;             // 0..NB_TAIL-1
    int zi = tb*blockDim.x + threadIdx.x;
    if (zi < NC) g_cnt[zi] = 0;
    __shared__ int sh_total;
    if (wl == 0) {
      int acc = 0;
      for (int q = lane; q < NCA; q += 32) acc += g_coarseA[q];
      for (int q = lane; q < NFW; q += 32) acc += g_fineW[q];
      int tot = warp_sum_bcast(acc);
      if (lane == 0) sh_total = tot;
    }
    __syncthreads();
    int total = sh_total;
    int stride = NB_TAIL * blockDim.x;
    for (int i = total + tb*blockDim.x + threadIdx.x; i < MP; i += stride) {
      out[i]        = 0.f;
      out[MP + i]   = 0.f;
      out[2*MP + i] = 0.f;
      out[3*MP + 3*i + 0] = 0.f;
      out[3*MP + 3*i + 1] = 0.f;
      out[3*MP + 3*i + 2] = 0.f;
      out[6*MP + i] = 0.f;
    }
  }
}

// ---------------- launch ----------------
extern "C" void kernel_launch(void* const* d_in, const int* in_sizes, int n_in,
                              void* d_out, int out_size) {
  const float* coords = nullptr;
  for (int i = 0; i < n_in; i++)
    if (in_sizes[i] == 3*NA) coords = (const float*)d_in[i];
  float* out = (float*)d_out;

  k_assign  <<<(NA + 255)/256, 256>>>(coords);            // cells + staging + bin reset
  k_sortcell<<<(NC + 7)/8, 256>>>();                      // per-cell id sort -> g_sp4
  k_pairs   <<<NC, 256>>>();                              // cell-centric smem pairs
  k_emit    <<<NBE_A + NBE_W + NB_TAIL, 256>>>(out);      // emit + tail
}